// round 6
// baseline (speedup 1.0000x reference)
#include <cuda_runtime.h>
#include <cstdint>

// SE(3) exp(xi) @ poses_init via bulk-async (TMA-class) tiles:
//   - per 256-pose tile: 2x cp.async.bulk loads (xi 6KB, poses 16KB) -> SMEM
//   - per-thread Rodrigues + compose, computed IN-PLACE in the pose tile
//     (output row 3 == pose row 3, so it is already correct in the buffer)
//   - 1x cp.async.bulk store (16KB) SMEM -> GMEM
// Rationale: LDG/STG variants were LSU/L1tex instruction-issue bound
// (11 LDG/STG per pose, DRAM stuck at ~64%); bulk copies bypass L1 and
// cost ~3 instructions per tile.
#define EPS_THETA 1e-6f
#define TILE 256
#define THREADS 256

#define XI_BYTES   (TILE * 6 * 4)    // 6144
#define POSE_BYTES (TILE * 16 * 4)   // 16384

struct __align__(16) SmemLayout {
    float  xi[TILE * 6];             // 6144 B
    float4 pose[TILE * 4];           // 16384 B, in-place output
    unsigned long long mbar;
};

__device__ __forceinline__ uint32_t s2u(const void* p) {
    return (uint32_t)__cvta_generic_to_shared(p);
}

__device__ __forceinline__ void mbar_init(uint32_t mbar, uint32_t count) {
    asm volatile("mbarrier.init.shared.b64 [%0], %1;" :: "r"(mbar), "r"(count) : "memory");
}
__device__ __forceinline__ void mbar_expect_tx(uint32_t mbar, uint32_t bytes) {
    asm volatile("mbarrier.arrive.expect_tx.shared.b64 _, [%0], %1;"
                 :: "r"(mbar), "r"(bytes) : "memory");
}
__device__ __forceinline__ void mbar_wait(uint32_t mbar, uint32_t parity) {
    asm volatile(
        "{\n\t"
        ".reg .pred P1;\n\t"
        "WAIT_LOOP_%=:\n\t"
        "mbarrier.try_wait.parity.acquire.cta.shared::cta.b64 P1, [%0], %1, 0x989680;\n\t"
        "@P1 bra.uni WAIT_DONE_%=;\n\t"
        "bra.uni WAIT_LOOP_%=;\n\t"
        "WAIT_DONE_%=:\n\t"
        "}"
        :: "r"(mbar), "r"(parity) : "memory");
}
__device__ __forceinline__ void bulk_load(uint32_t dst_smem, const void* src_gmem,
                                          uint32_t bytes, uint32_t mbar) {
    asm volatile(
        "cp.async.bulk.shared::cluster.global.mbarrier::complete_tx::bytes [%0], [%1], %2, [%3];"
        :: "r"(dst_smem), "l"(src_gmem), "r"(bytes), "r"(mbar) : "memory");
}
__device__ __forceinline__ void bulk_store(void* dst_gmem, uint32_t src_smem, uint32_t bytes) {
    asm volatile(
        "cp.async.bulk.global.shared::cta.bulk_group [%0], [%1], %2;"
        :: "l"(dst_gmem), "r"(src_smem), "r"(bytes) : "memory");
}

__device__ __forceinline__ float4 f4_fma(float a, float4 x, float4 acc) {
    acc.x = fmaf(a, x.x, acc.x);
    acc.y = fmaf(a, x.y, acc.y);
    acc.z = fmaf(a, x.z, acc.z);
    acc.w = fmaf(a, x.w, acc.w);
    return acc;
}
__device__ __forceinline__ float4 f4_scale(float a, float4 x) {
    return make_float4(a * x.x, a * x.y, a * x.z, a * x.w);
}

// Branchless Rodrigues without normalization:
// R = I + A*W + B*W^2, W = skew(w), W^2 = w w^T - theta^2 I
__device__ __forceinline__ void se3_rows(
    float tx, float ty, float tz, float wx, float wy, float wz,
    float4 p0, float4 p1, float4 p2, float4 p3,
    float4& o0, float4& o1, float4& o2)
{
    float theta2 = wx*wx + wy*wy + wz*wz;
    float theta  = sqrtf(theta2);
    bool  small  = theta < EPS_THETA;
    float A = small ? 1.0f : sinf(theta) / theta;
    float B = small ? 0.0f : (1.0f - cosf(theta)) / theta2;

    float R00 = 1.0f + B * (wx*wx - theta2);
    float R11 = 1.0f + B * (wy*wy - theta2);
    float R22 = 1.0f + B * (wz*wz - theta2);
    float bxy = B*wx*wy, bxz = B*wx*wz, byz = B*wy*wz;
    float awx = A*wx, awy = A*wy, awz = A*wz;
    float R01 = bxy - awz, R02 = bxz + awy;
    float R10 = bxy + awz, R12 = byz - awx;
    float R20 = bxz - awy, R21 = byz + awx;

    o0 = f4_scale(R00, p0);
    o0 = f4_fma(R01, p1, o0); o0 = f4_fma(R02, p2, o0); o0 = f4_fma(tx, p3, o0);
    o1 = f4_scale(R10, p0);
    o1 = f4_fma(R11, p1, o1); o1 = f4_fma(R12, p2, o1); o1 = f4_fma(ty, p3, o1);
    o2 = f4_scale(R20, p0);
    o2 = f4_fma(R21, p1, o2); o2 = f4_fma(R22, p2, o2); o2 = f4_fma(tz, p3, o2);
}

__global__ void __launch_bounds__(THREADS) se3_bulk_kernel(
    const float*  __restrict__ xi,      // [N, 6]
    const float4* __restrict__ poses,   // [N, 4] rows
    float4*       __restrict__ out,     // [N, 4] rows
    int n)
{
    __shared__ SmemLayout sm;
    int tid  = threadIdx.x;
    long base = (long)blockIdx.x * TILE;
    int cnt  = (int)min((long)TILE, (long)n - base);

    if (cnt == TILE) {
        // ---- full tile: bulk pipeline ----
        uint32_t mbar = s2u(&sm.mbar);
        if (tid == 0) mbar_init(mbar, 1);
        __syncthreads();
        if (tid == 0) {
            mbar_expect_tx(mbar, XI_BYTES + POSE_BYTES);
            bulk_load(s2u(sm.xi),   xi    + base * 6, XI_BYTES,   mbar);
            bulk_load(s2u(sm.pose), poses + base * 4, POSE_BYTES, mbar);
        }
        mbar_wait(mbar, 0);

        // compute in-place: each thread owns one pose
        const float2* xr = reinterpret_cast<const float2*>(&sm.xi[tid * 6]);
        float2 a0 = xr[0], a1 = xr[1], a2 = xr[2];
        float4 p0 = sm.pose[tid * 4 + 0];
        float4 p1 = sm.pose[tid * 4 + 1];
        float4 p2 = sm.pose[tid * 4 + 2];
        float4 p3 = sm.pose[tid * 4 + 3];

        float4 o0, o1, o2;
        se3_rows(a0.x, a0.y, a1.x, a1.y, a2.x, a2.y, p0, p1, p2, p3, o0, o1, o2);

        sm.pose[tid * 4 + 0] = o0;
        sm.pose[tid * 4 + 1] = o1;
        sm.pose[tid * 4 + 2] = o2;
        // row 3 already equals p3 in the buffer — no store needed

        __syncthreads();
        if (tid == 0) {
            asm volatile("fence.proxy.async.shared::cta;" ::: "memory");
            bulk_store(out + base * 4, s2u(sm.pose), POSE_BYTES);
            asm volatile("cp.async.bulk.commit_group;" ::: "memory");
            asm volatile("cp.async.bulk.wait_group 0;" ::: "memory");
        }
    } else {
        // ---- tail tile: direct global path ----
        for (int i = tid; i < cnt; i += THREADS) {
            long g = base + i;
            const float2* xr = reinterpret_cast<const float2*>(xi + g * 6);
            float2 a0 = xr[0], a1 = xr[1], a2 = xr[2];
            const float4* P = poses + g * 4;
            float4 p0 = P[0], p1 = P[1], p2 = P[2], p3 = P[3];
            float4 o0, o1, o2;
            se3_rows(a0.x, a0.y, a1.x, a1.y, a2.x, a2.y, p0, p1, p2, p3, o0, o1, o2);
            float4* O = out + g * 4;
            O[0] = o0; O[1] = o1; O[2] = o2; O[3] = p3;
        }
    }
}

extern "C" void kernel_launch(void* const* d_in, const int* in_sizes, int n_in,
                              void* d_out, int out_size) {
    const float*  xi    = (const float*)d_in[0];   // [N,6]
    const float4* poses = (const float4*)d_in[1];  // [N,4,4] rows of float4
    float4*       out   = (float4*)d_out;
    int n = in_sizes[0] / 6;
    int blocks = (n + TILE - 1) / TILE;
    se3_bulk_kernel<<<blocks, THREADS>>>(xi, poses, out, n);
}